// round 1
// baseline (speedup 1.0000x reference)
#include <cuda_runtime.h>
#include <math.h>

// Problem constants
#define BB   32
#define SS   1024
#define DD   3
#define NF   512
#define NS   64
#define HID  100
#define FSZ  256

// Decomposition
#define NSC  8            // S chunks
#define SCH  (SS/NSC)     // 128 steps per chunk
#define NFC  4            // nf chunks
#define FCH  (NF/NFC)     // 128 nf per block (= threads)

// Scratch (device globals: allocation-free per harness rules)
__device__ float g_H[NF*HID];
__device__ float g_F[NF*FSZ];
__device__ float g_Womg[NF*3];
__device__ float g_totC[BB*NSC*NF];
__device__ float g_totS[BB*NSC*NF];
__device__ float g_part[(size_t)BB*SS*16];

// ---------------- Fourier-feature MLP (tiny) ----------------

__global__ void k_hidden(const float* __restrict__ noise,
                         const float* __restrict__ W1,
                         const float* __restrict__ b1) {
    int idx = blockIdx.x*blockDim.x + threadIdx.x;
    if (idx >= NF*HID) return;
    int f = idx / HID, j = idx % HID;
    float acc = b1[j];
    const float* nrow = noise + f*NS;
    #pragma unroll 8
    for (int k = 0; k < NS; k++) acc = fmaf(nrow[k], W1[k*HID + j], acc);
    g_H[idx] = tanhf(acc);
}

__global__ void k_fourier(const float* __restrict__ W2,
                          const float* __restrict__ b2) {
    int idx = blockIdx.x*blockDim.x + threadIdx.x;
    if (idx >= NF*FSZ) return;
    int f = idx / FSZ, i = idx % FSZ;
    float acc = b2[i];
    const float* h = g_H + f*HID;
    #pragma unroll 4
    for (int j = 0; j < HID; j++) acc = fmaf(h[j], W2[j*FSZ + i], acc);
    g_F[idx] = tanhf(acc);
}

__global__ void k_womg(const float* __restrict__ W) {
    int n = blockIdx.x*blockDim.x + threadIdx.x;
    if (n >= NF) return;
    float w0 = 0.f, w1 = 0.f, w2 = 0.f;
    const float* frow = g_F + n*FSZ;
    #pragma unroll 4
    for (int i = 0; i < FSZ; i++) {
        float fv = frow[i];
        w0 = fmaf(fv, W[i*3+0], w0);
        w1 = fmaf(fv, W[i*3+1], w1);
        w2 = fmaf(fv, W[i*3+2], w2);
    }
    g_Womg[n*3+0] = w0;
    g_Womg[n*3+1] = w1;
    g_Womg[n*3+2] = w2;
}

// ---------------- Pass A: per-S-chunk trig totals ----------------

__global__ void __launch_bounds__(FCH) k_passA(const float* __restrict__ X) {
    int t  = threadIdx.x;
    int fc = blockIdx.x, sc = blockIdx.y, b = blockIdx.z;
    int n  = fc*FCH + t;
    float w0 = g_Womg[n*3+0], w1 = g_Womg[n*3+1], w2 = g_Womg[n*3+2];

    __shared__ float sx[SCH*3];
    int s0 = sc*SCH;
    const float* xp = X + ((size_t)b*SS + s0)*3;
    for (int i = t; i < SCH*3; i += FCH) sx[i] = xp[i];
    __syncthreads();

    float sumC = 0.f, sumS = 0.f;
    #pragma unroll 4
    for (int k = 0; k < SCH; k++) {
        float th = fmaf(sx[k*3+2], w2, fmaf(sx[k*3+1], w1, sx[k*3]*w0));
        float sv, cv;
        sincosf(th, &sv, &cv);
        sumC += cv; sumS += sv;
    }
    g_totC[(b*NSC + sc)*NF + n] = sumC;
    g_totS[(b*NSC + sc)*NF + n] = sumS;
}

// ---------------- Pass C: contributions with scan offsets ----------------

__global__ void __launch_bounds__(FCH) k_passC(const float* __restrict__ X) {
    int t  = threadIdx.x;
    int fc = blockIdx.x, sc = blockIdx.y, b = blockIdx.z;
    int n  = fc*FCH + t;
    float w0 = g_Womg[n*3+0], w1 = g_Womg[n*3+1], w2 = g_Womg[n*3+2];

    // exclusive offsets from preceding S chunks
    float runC = 0.f, runS = 0.f;
    for (int p = 0; p < sc; p++) {
        runC += g_totC[(b*NSC + p)*NF + n];
        runS += g_totS[(b*NSC + p)*NF + n];
    }

    __shared__ float sx[SCH*3];
    int s0 = sc*SCH;
    const float* xp = X + ((size_t)b*SS + s0)*3;
    for (int i = t; i < SCH*3; i += FCH) sx[i] = xp[i];
    __syncthreads();

    int lane = t & 31, warp = t >> 5;
    int slot = fc*4 + warp;

    for (int k = 0; k < SCH; k++) {
        float th = fmaf(sx[k*3+2], w2, fmaf(sx[k*3+1], w1, sx[k*3]*w0));
        float sv, cv;
        sincosf(th, &sv, &cv);
        float contrib = cv*runC + sv*runS;   // uses EXCLUSIVE prefix
        runC += cv; runS += sv;
        #pragma unroll
        for (int o = 16; o; o >>= 1)
            contrib += __shfl_xor_sync(0xffffffffu, contrib, o);
        if (lane == 0)
            g_part[((size_t)(b*SS + s0 + k))*16 + slot] = contrib;
    }
}

// ---------------- Final: lam + loglik ----------------

__global__ void k_final(const float* __restrict__ X,
                        const float* __restrict__ alpha,
                        float* __restrict__ out) {
    int idx = blockIdx.x*blockDim.x + threadIdx.x;
    if (idx >= BB*SS) return;
    const float* p = g_part + (size_t)idx*16;
    float s = 0.f;
    #pragma unroll
    for (int i = 0; i < 16; i++) s += p[i];
    float lam = fmaf(alpha[0], s * (1.0f/NF), 10.0f);
    out[idx] = lam;

    int b = idx / SS, si = idx % SS;
    float x0 = X[(size_t)idx*3];
    float mask = (x0 > 0.f) ? 1.f : 0.f;
    const float C2 = -3947.8417604357433f;   // -MU*T*(2*pi)^(D-1)
    out[BB*SS + b*(SS+1) + si] = logf(lam)*mask + C2;
    if (idx < BB)                             // extra (S+1)-th column
        out[BB*SS + idx*(SS+1) + SS] = C2;
}

// ---------------- Launch ----------------

extern "C" void kernel_launch(void* const* d_in, const int* in_sizes, int n_in,
                              void* d_out, int out_size) {
    const float* X     = (const float*)d_in[0];
    const float* noise = (const float*)d_in[1];
    const float* W1    = (const float*)d_in[2];
    const float* b1    = (const float*)d_in[3];
    const float* W2    = (const float*)d_in[4];
    const float* b2    = (const float*)d_in[5];
    const float* W     = (const float*)d_in[6];
    const float* alpha = (const float*)d_in[7];
    float* out = (float*)d_out;

    k_hidden <<<(NF*HID + 255)/256, 256>>>(noise, W1, b1);
    k_fourier<<<(NF*FSZ + 255)/256, 256>>>(W2, b2);
    k_womg   <<<(NF + 255)/256, 256>>>(W);

    dim3 grid(NFC, NSC, BB);
    k_passA<<<grid, FCH>>>(X);
    k_passC<<<grid, FCH>>>(X);

    k_final<<<(BB*SS + 255)/256, 256>>>(X, alpha, out);
}

// round 2
// speedup vs baseline: 1.0040x; 1.0040x over previous
#include <cuda_runtime.h>
#include <math.h>

// Problem constants
#define BB   32
#define SS   1024
#define DD   3
#define NF   512
#define NS   64
#define HID  100
#define FSZ  256

// Decomposition
#define NSC  8            // S chunks
#define SCH  (SS/NSC)     // 128 steps per chunk
#define NFC  4            // nf chunks
#define FCH  (NF/NFC)     // 128 nf per block (= threads)

// Scratch (device globals: allocation-free per harness rules)
__device__ float g_H[NF*HID];
__device__ float g_F[NF*FSZ];
__device__ float g_Womg[NF*3];
__device__ float g_totC[BB*NSC*NF];
__device__ float g_totS[BB*NSC*NF];
__device__ float g_part[(size_t)BB*SS*16];

// ---------------- Fourier-feature MLP (tiny) ----------------

__global__ void k_hidden(const float* __restrict__ noise,
                         const float* __restrict__ W1,
                         const float* __restrict__ b1) {
    int idx = blockIdx.x*blockDim.x + threadIdx.x;
    if (idx >= NF*HID) return;
    int f = idx / HID, j = idx % HID;
    float acc = b1[j];
    const float* nrow = noise + f*NS;
    #pragma unroll 8
    for (int k = 0; k < NS; k++) acc = fmaf(nrow[k], W1[k*HID + j], acc);
    g_H[idx] = tanhf(acc);
}

__global__ void k_fourier(const float* __restrict__ W2,
                          const float* __restrict__ b2) {
    int idx = blockIdx.x*blockDim.x + threadIdx.x;
    if (idx >= NF*FSZ) return;
    int f = idx / FSZ, i = idx % FSZ;
    float acc = b2[i];
    const float* h = g_H + f*HID;
    #pragma unroll 4
    for (int j = 0; j < HID; j++) acc = fmaf(h[j], W2[j*FSZ + i], acc);
    g_F[idx] = tanhf(acc);
}

__global__ void k_womg(const float* __restrict__ W) {
    int n = blockIdx.x*blockDim.x + threadIdx.x;
    if (n >= NF) return;
    float w0 = 0.f, w1 = 0.f, w2 = 0.f;
    const float* frow = g_F + n*FSZ;
    #pragma unroll 4
    for (int i = 0; i < FSZ; i++) {
        float fv = frow[i];
        w0 = fmaf(fv, W[i*3+0], w0);
        w1 = fmaf(fv, W[i*3+1], w1);
        w2 = fmaf(fv, W[i*3+2], w2);
    }
    g_Womg[n*3+0] = w0;
    g_Womg[n*3+1] = w1;
    g_Womg[n*3+2] = w2;
}

// ---------------- Pass A: per-S-chunk trig totals ----------------

__global__ void __launch_bounds__(FCH) k_passA(const float* __restrict__ X) {
    int t  = threadIdx.x;
    int fc = blockIdx.x, sc = blockIdx.y, b = blockIdx.z;
    int n  = fc*FCH + t;
    float w0 = g_Womg[n*3+0], w1 = g_Womg[n*3+1], w2 = g_Womg[n*3+2];

    __shared__ float sx[SCH*3];
    int s0 = sc*SCH;
    const float* xp = X + ((size_t)b*SS + s0)*3;
    for (int i = t; i < SCH*3; i += FCH) sx[i] = xp[i];
    __syncthreads();

    float sumC = 0.f, sumS = 0.f;
    #pragma unroll 4
    for (int k = 0; k < SCH; k++) {
        float th = fmaf(sx[k*3+2], w2, fmaf(sx[k*3+1], w1, sx[k*3]*w0));
        float sv, cv;
        sincosf(th, &sv, &cv);
        sumC += cv; sumS += sv;
    }
    g_totC[(b*NSC + sc)*NF + n] = sumC;
    g_totS[(b*NSC + sc)*NF + n] = sumS;
}

// ---------------- Pass C: contributions with scan offsets ----------------

__global__ void __launch_bounds__(FCH) k_passC(const float* __restrict__ X) {
    int t  = threadIdx.x;
    int fc = blockIdx.x, sc = blockIdx.y, b = blockIdx.z;
    int n  = fc*FCH + t;
    float w0 = g_Womg[n*3+0], w1 = g_Womg[n*3+1], w2 = g_Womg[n*3+2];

    // exclusive offsets from preceding S chunks
    float runC = 0.f, runS = 0.f;
    for (int p = 0; p < sc; p++) {
        runC += g_totC[(b*NSC + p)*NF + n];
        runS += g_totS[(b*NSC + p)*NF + n];
    }

    __shared__ float sx[SCH*3];
    int s0 = sc*SCH;
    const float* xp = X + ((size_t)b*SS + s0)*3;
    for (int i = t; i < SCH*3; i += FCH) sx[i] = xp[i];
    __syncthreads();

    int lane = t & 31, warp = t >> 5;
    int slot = fc*4 + warp;

    for (int k = 0; k < SCH; k++) {
        float th = fmaf(sx[k*3+2], w2, fmaf(sx[k*3+1], w1, sx[k*3]*w0));
        float sv, cv;
        sincosf(th, &sv, &cv);
        float contrib = cv*runC + sv*runS;   // uses EXCLUSIVE prefix
        runC += cv; runS += sv;
        #pragma unroll
        for (int o = 16; o; o >>= 1)
            contrib += __shfl_xor_sync(0xffffffffu, contrib, o);
        if (lane == 0)
            g_part[((size_t)(b*SS + s0 + k))*16 + slot] = contrib;
    }
}

// ---------------- Final: lam + loglik ----------------

__global__ void k_final(const float* __restrict__ X,
                        const float* __restrict__ alpha,
                        float* __restrict__ out) {
    int idx = blockIdx.x*blockDim.x + threadIdx.x;
    if (idx >= BB*SS) return;
    const float* p = g_part + (size_t)idx*16;
    float s = 0.f;
    #pragma unroll
    for (int i = 0; i < 16; i++) s += p[i];
    float lam = fmaf(alpha[0], s * (1.0f/NF), 10.0f);
    out[idx] = lam;

    int b = idx / SS, si = idx % SS;
    float x0 = X[(size_t)idx*3];
    float mask = (x0 > 0.f) ? 1.f : 0.f;
    const float C2 = -3947.8417604357433f;   // -MU*T*(2*pi)^(D-1)
    out[BB*SS + b*(SS+1) + si] = logf(lam)*mask + C2;
    if (idx < BB)                             // extra (S+1)-th column
        out[BB*SS + idx*(SS+1) + SS] = C2;
}

// ---------------- Launch ----------------

extern "C" void kernel_launch(void* const* d_in, const int* in_sizes, int n_in,
                              void* d_out, int out_size) {
    const float* X     = (const float*)d_in[0];
    const float* noise = (const float*)d_in[1];
    const float* W1    = (const float*)d_in[2];
    const float* b1    = (const float*)d_in[3];
    const float* W2    = (const float*)d_in[4];
    const float* b2    = (const float*)d_in[5];
    const float* W     = (const float*)d_in[6];
    const float* alpha = (const float*)d_in[7];
    float* out = (float*)d_out;

    k_hidden <<<(NF*HID + 255)/256, 256>>>(noise, W1, b1);
    k_fourier<<<(NF*FSZ + 255)/256, 256>>>(W2, b2);
    k_womg   <<<(NF + 255)/256, 256>>>(W);

    dim3 grid(NFC, NSC, BB);
    k_passA<<<grid, FCH>>>(X);
    k_passC<<<grid, FCH>>>(X);

    k_final<<<(BB*SS + 255)/256, 256>>>(X, alpha, out);
}